// round 2
// baseline (speedup 1.0000x reference)
#include <cuda_runtime.h>
#include <cuda_bf16.h>

// B rows of x:(B,4) f32. Three MLPs 3->4->1 (relu -> sigmoid), routed by
// sel = x[:,1] in {0,1,2}. Key identity: net n's output is only selected
// when sel == n, so fold W1[1,:]*n into the bias and drop that input term.
//
// Layout per net in smem (17 floats): a[4]=W1[0,:], c[4]=W1[2,:],
// beff[4]=b1+n*W1[1,:], W2[4], b2.

#define ROWS 4

__global__ __launch_bounds__(256) void Program_72902774882571_kernel(
    const float4* __restrict__ x,
    const float* __restrict__ Ws1, const float* __restrict__ bs1,
    const float* __restrict__ Ws2, const float* __restrict__ bs2,
    const float* __restrict__ Wu1, const float* __restrict__ bu1,
    const float* __restrict__ Wu2, const float* __restrict__ bu2,
    const float* __restrict__ Wd1, const float* __restrict__ bd1,
    const float* __restrict__ Wd2, const float* __restrict__ bd2,
    float* __restrict__ out, int B, int T)
{
    __shared__ float w[51];
    int tid = threadIdx.x;

    if (tid < 96) {
        int n = tid >> 5, ln = tid & 31;
        if (ln < 17) {
            const float* W1 = (n == 0) ? Ws1 : (n == 1) ? Wu1 : Wd1;
            const float* b1 = (n == 0) ? bs1 : (n == 1) ? bu1 : bd1;
            const float* W2 = (n == 0) ? Ws2 : (n == 1) ? Wu2 : Wd2;
            const float* b2 = (n == 0) ? bs2 : (n == 1) ? bu2 : bd2;
            float v;
            if (ln < 4)        v = W1[0 * 4 + ln];                       // a_j
            else if (ln < 8)   v = W1[2 * 4 + (ln - 4)];                 // c_j
            else if (ln < 12)  v = b1[ln - 8] + (float)n * W1[1 * 4 + (ln - 8)];
            else if (ln < 16)  v = W2[ln - 12];
            else               v = b2[0];
            w[n * 17 + ln] = v;
        }
    }
    __syncthreads();

    int t = blockIdx.x * blockDim.x + tid;

    float4 xs[ROWS];
#pragma unroll
    for (int k = 0; k < ROWS; ++k) {
        int r = t + k * T;
        if (r < B) xs[k] = x[r];
    }

    float res[ROWS];
#pragma unroll
    for (int k = 0; k < ROWS; ++k) {
        float x0 = xs[k].x, sel = xs[k].y, x2 = xs[k].z;
        float z[3];
#pragma unroll
        for (int n = 0; n < 3; ++n) {
            const float* wn = &w[n * 17];
            float acc = wn[16];
#pragma unroll
            for (int j = 0; j < 4; ++j) {
                float h = fmaf(x0, wn[j], fmaf(x2, wn[4 + j], wn[8 + j]));
                h = fmaxf(h, 0.0f);
                acc = fmaf(h, wn[12 + j], acc);
            }
            z[n] = acc;
        }
        float zz = (sel == 0.0f) ? z[0] : ((sel == 1.0f) ? z[1] : z[2]);
        float sig = 1.0f / (1.0f + __expf(-zz));
        bool valid = (sel == 0.0f) || (sel == 1.0f) || (sel == 2.0f);
        res[k] = valid ? sig : 0.0f;
    }

#pragma unroll
    for (int k = 0; k < ROWS; ++k) {
        int r = t + k * T;
        if (r < B) out[r] = res[k];
    }
}

extern "C" void kernel_launch(void* const* d_in, const int* in_sizes, int n_in,
                              void* d_out, int out_size)
{
    const float4* x  = (const float4*)d_in[0];
    const float* Ws1 = (const float*)d_in[1];
    const float* bs1 = (const float*)d_in[2];
    const float* Ws2 = (const float*)d_in[3];
    const float* bs2 = (const float*)d_in[4];
    const float* Wu1 = (const float*)d_in[5];
    const float* bu1 = (const float*)d_in[6];
    const float* Wu2 = (const float*)d_in[7];
    const float* bu2 = (const float*)d_in[8];
    const float* Wd1 = (const float*)d_in[9];
    const float* bd1 = (const float*)d_in[10];
    const float* Wd2 = (const float*)d_in[11];
    const float* bd2 = (const float*)d_in[12];

    int B = in_sizes[0] / 4;                 // rows
    int threads = 256;
    int T = (B + ROWS - 1) / ROWS;           // total threads (stride)
    int blocks = (T + threads - 1) / threads;
    T = blocks * threads;                    // actual stride = launched threads

    Program_72902774882571_kernel<<<blocks, threads>>>(
        x, Ws1, bs1, Ws2, bs2, Wu1, bu1, Wu2, bu2, Wd1, bd1, Wd2, bd2,
        (float*)d_out, B, T);
}

// round 3
// speedup vs baseline: 1.0269x; 1.0269x over previous
#include <cuda_runtime.h>
#include <cuda_bf16.h>

// B rows of x:(B,4) f32; out[r] = sigmoid(MLP_{sel}(x[:,{0,1,2}])) where
// sel = x[:,1] in {0,1,2}. Only the selected net is evaluated (indexed via
// smem). Bias fold: when net n is selected, x1 == n exactly, so
// beff = b1 + n*W1[1,:] absorbs the x1 term.
//
// smem layout per net (stride 17): [0:4) a=W1[0,:], [4:8) c=W1[2,:],
// [8:12) beff, [12:16) W2, [16] b2.

__global__ __launch_bounds__(256) void Program_72902774882571_kernel(
    const float4* __restrict__ x,
    const float* __restrict__ Ws1, const float* __restrict__ bs1,
    const float* __restrict__ Ws2, const float* __restrict__ bs2,
    const float* __restrict__ Wu1, const float* __restrict__ bu1,
    const float* __restrict__ Wu2, const float* __restrict__ bu2,
    const float* __restrict__ Wd1, const float* __restrict__ bd1,
    const float* __restrict__ Wd2, const float* __restrict__ bd2,
    float* __restrict__ out, int B)
{
    __shared__ float w[51];
    int tid = threadIdx.x;

    if (tid < 96) {
        int n = tid >> 5, ln = tid & 31;
        if (ln < 17) {
            const float* W1 = (n == 0) ? Ws1 : (n == 1) ? Wu1 : Wd1;
            const float* b1 = (n == 0) ? bs1 : (n == 1) ? bu1 : bd1;
            const float* W2 = (n == 0) ? Ws2 : (n == 1) ? Wu2 : Wd2;
            const float* b2 = (n == 0) ? bs2 : (n == 1) ? bu2 : bd2;
            float v;
            if (ln < 4)        v = W1[0 * 4 + ln];                         // a_j
            else if (ln < 8)   v = W1[2 * 4 + (ln - 4)];                   // c_j
            else if (ln < 12)  v = b1[ln - 8] + (float)n * W1[1 * 4 + (ln - 8)];
            else if (ln < 16)  v = W2[ln - 12];
            else               v = b2[0];
            w[n * 17 + ln] = v;
        }
    }
    __syncthreads();

    int r = blockIdx.x * blockDim.x + tid;
    if (r >= B) return;

    float4 xr = x[r];
    float x0 = xr.x, sel = xr.y, x2 = xr.z;

    int idx = (int)sel;
    idx = (idx < 0) ? 0 : (idx > 2 ? 2 : idx);
    const float* wn = &w[idx * 17];

    float acc = wn[16];
#pragma unroll
    for (int j = 0; j < 4; ++j) {
        float h = fmaf(x0, wn[j], fmaf(x2, wn[4 + j], wn[8 + j]));
        h = fmaxf(h, 0.0f);
        acc = fmaf(h, wn[12 + j], acc);
    }

    float sig = __fdividef(1.0f, 1.0f + __expf(-acc));
    bool valid = (sel == 0.0f) || (sel == 1.0f) || (sel == 2.0f);
    out[r] = valid ? sig : 0.0f;
}

extern "C" void kernel_launch(void* const* d_in, const int* in_sizes, int n_in,
                              void* d_out, int out_size)
{
    const float4* x  = (const float4*)d_in[0];
    const float* Ws1 = (const float*)d_in[1];
    const float* bs1 = (const float*)d_in[2];
    const float* Ws2 = (const float*)d_in[3];
    const float* bs2 = (const float*)d_in[4];
    const float* Wu1 = (const float*)d_in[5];
    const float* bu1 = (const float*)d_in[6];
    const float* Wu2 = (const float*)d_in[7];
    const float* bu2 = (const float*)d_in[8];
    const float* Wd1 = (const float*)d_in[9];
    const float* bd1 = (const float*)d_in[10];
    const float* Wd2 = (const float*)d_in[11];
    const float* bd2 = (const float*)d_in[12];

    int B = in_sizes[0] / 4;   // rows
    int threads = 256;
    int blocks = (B + threads - 1) / threads;

    Program_72902774882571_kernel<<<blocks, threads>>>(
        x, Ws1, bs1, Ws2, bs2, Wu1, bu1, Wu2, bu2, Wd1, bd1, Wd2, bd2,
        (float*)d_out, B);
}

// round 4
// speedup vs baseline: 1.2120x; 1.1803x over previous
#include <cuda_runtime.h>
#include <cuda_bf16.h>

// B rows of x:(B,4) f32; out[r] = sigmoid(MLP_{sel}(x)) with sel = x[:,1]
// in {0,1,2} selecting one of three 3->4->1 nets. Only the selected net is
// evaluated; since x1 == n exactly when net n is selected, the x1 term is
// folded into the bias: beff = b1 + n*W1[1,:].
//
// Persistent-ish grid: 1024 blocks (one wave), weights staged in smem once,
// grid-stride loop with inner unroll of 4 coalesced float4 loads.

#define UNROLL 4

__global__ __launch_bounds__(256) void Program_72902774882571_kernel(
    const float4* __restrict__ x,
    const float* __restrict__ Ws1, const float* __restrict__ bs1,
    const float* __restrict__ Ws2, const float* __restrict__ bs2,
    const float* __restrict__ Wu1, const float* __restrict__ bu1,
    const float* __restrict__ Wu2, const float* __restrict__ bu2,
    const float* __restrict__ Wd1, const float* __restrict__ bd1,
    const float* __restrict__ Wd2, const float* __restrict__ bd2,
    float* __restrict__ out, int B)
{
    __shared__ float w[51];
    int tid = threadIdx.x;

    if (tid < 96) {
        int n = tid >> 5, ln = tid & 31;
        if (ln < 17) {
            const float* W1 = (n == 0) ? Ws1 : (n == 1) ? Wu1 : Wd1;
            const float* b1 = (n == 0) ? bs1 : (n == 1) ? bu1 : bd1;
            const float* W2 = (n == 0) ? Ws2 : (n == 1) ? Wu2 : Wd2;
            const float* b2 = (n == 0) ? bs2 : (n == 1) ? bu2 : bd2;
            float v;
            if (ln < 4)        v = W1[0 * 4 + ln];                         // a_j
            else if (ln < 8)   v = W1[2 * 4 + (ln - 4)];                   // c_j
            else if (ln < 12)  v = b1[ln - 8] + (float)n * W1[1 * 4 + (ln - 8)];
            else if (ln < 16)  v = W2[ln - 12];
            else               v = b2[0];
            w[n * 17 + ln] = v;
        }
    }
    __syncthreads();

    const int T = gridDim.x * blockDim.x;           // total threads
    int base = blockIdx.x * blockDim.x + tid;

    for (int r0 = base; r0 < B; r0 += UNROLL * T) {
        float4 xs[UNROLL];
#pragma unroll
        for (int k = 0; k < UNROLL; ++k) {
            int r = r0 + k * T;
            if (r < B) xs[k] = x[r];
        }

#pragma unroll
        for (int k = 0; k < UNROLL; ++k) {
            int r = r0 + k * T;
            if (r >= B) break;
            float x0 = xs[k].x, sel = xs[k].y, x2 = xs[k].z;

            int idx = (int)sel;
            idx = (idx < 0) ? 0 : (idx > 2 ? 2 : idx);
            const float* wn = &w[idx * 17];

            float acc = wn[16];
#pragma unroll
            for (int j = 0; j < 4; ++j) {
                float h = fmaf(x0, wn[j], fmaf(x2, wn[4 + j], wn[8 + j]));
                h = fmaxf(h, 0.0f);
                acc = fmaf(h, wn[12 + j], acc);
            }

            float sig = __fdividef(1.0f, 1.0f + __expf(-acc));
            bool valid = (sel == 0.0f) || (sel == 1.0f) || (sel == 2.0f);
            out[r] = valid ? sig : 0.0f;
        }
    }
}

extern "C" void kernel_launch(void* const* d_in, const int* in_sizes, int n_in,
                              void* d_out, int out_size)
{
    const float4* x  = (const float4*)d_in[0];
    const float* Ws1 = (const float*)d_in[1];
    const float* bs1 = (const float*)d_in[2];
    const float* Ws2 = (const float*)d_in[3];
    const float* bs2 = (const float*)d_in[4];
    const float* Wu1 = (const float*)d_in[5];
    const float* bu1 = (const float*)d_in[6];
    const float* Wu2 = (const float*)d_in[7];
    const float* bu2 = (const float*)d_in[8];
    const float* Wd1 = (const float*)d_in[9];
    const float* bd1 = (const float*)d_in[10];
    const float* Wd2 = (const float*)d_in[11];
    const float* bd2 = (const float*)d_in[12];

    int B = in_sizes[0] / 4;   // rows
    int threads = 256;
    int blocks = 1024;          // one wave on 148 SMs (8 blocks/SM @ 32 regs)
    int max_blocks = (B + threads - 1) / threads;
    if (blocks > max_blocks) blocks = max_blocks;

    Program_72902774882571_kernel<<<blocks, threads>>>(
        x, Ws1, bs1, Ws2, bs2, Wu1, bu1, Wu2, bu2, Wd1, bd1, Wd2, bd2,
        (float*)d_out, B);
}